// round 7
// baseline (speedup 1.0000x reference)
#include <cuda_runtime.h>

// Problem constants (fixed by the dataset)
#define BB 16
#define TT 128
#define UU 64
#define VV 1024
#define CELLS (BB * TT * UU)      // 131072
#define NEGF   (-1e30f)
#define LOG2EF 1.4426950408889634f
#define LN2F   0.6931471805599453f

// Scratch (allocation-free rule: __device__ globals)
// lp tables stored PRE-SCALED by log2(e) (log2-domain DP).
__device__ float g_lpb[CELLS];    // lp_blank * log2e
__device__ float g_lpl[CELLS];    // lp_label * log2e (u < UU-1 valid)
__device__ float g_cost[BB];
__device__ int   g_ticket;        // last-block-done counter (zero-init; winner resets)

// ---------------------------------------------------------------------------
// FFMA-only expf (phase-1 bulk): avoids MUFU throughput wall at 134M ops.
// ---------------------------------------------------------------------------
__device__ __forceinline__ float fexp(float x) {
    const float C1    = 1.4426950408889634f;
    const float MAGIC = 12582912.0f;           // 1.5 * 2^23
    float z = fmaf(x, C1, MAGIC);
    float d = MAGIC - z;
    float f = fmaf(x, C1, d);
    float p = fmaf(f, 0.0096181291076285f, 0.0555041086648216f);
    p = fmaf(f, p, 0.2402265069591007f);
    p = fmaf(f, p, 0.6931471805599453f);
    p = fmaf(f, p, 1.0f);
    return __int_as_float(__float_as_int(p) + (__float_as_int(z) << 23));
}

__device__ __forceinline__ float fast_ex2(float x) {
    float r; asm("ex2.approx.ftz.f32 %0, %1;" : "=f"(r) : "f"(x)); return r;
}
__device__ __forceinline__ float fast_lg2(float x) {
    float r; asm("lg2.approx.ftz.f32 %0, %1;" : "=f"(r) : "f"(x)); return r;
}

// ---------------------------------------------------------------------------
// Phase 1: one warp per (b,t,u) cell; 8 front-batched float4 streaming loads.
// At 86.6% DRAM — the streaming floor; unchanged.
// ---------------------------------------------------------------------------
__global__ void __launch_bounds__(256) lse_kernel(const float* __restrict__ acts,
                                                  const int*   __restrict__ labels) {
    int warp = blockIdx.x * 8 + (threadIdx.x >> 5);
    int lane = threadIdx.x & 31;
    const float*  base = acts + (size_t)warp * VV;
    const float4* p4   = (const float4*)base;

    float4 v[8];
#pragma unroll
    for (int i = 0; i < 8; i++)
        v[i] = __ldcs(&p4[i * 32 + lane]);

    float blank = v[0].x;                      // valid on lane 0 only
    float s0 = 0.f, s1 = 0.f, s2 = 0.f, s3 = 0.f;
#pragma unroll
    for (int i = 0; i < 8; i++) {
        s0 += fexp(v[i].x);
        s1 += fexp(v[i].y);
        s2 += fexp(v[i].z);
        s3 += fexp(v[i].w);
    }
    float s = (s0 + s1) + (s2 + s3);
#pragma unroll
    for (int o = 16; o; o >>= 1)
        s += __shfl_xor_sync(0xffffffffu, s, o);

    float lse2 = fast_lg2(s);                  // log2-domain lse

    if (lane == 0) {
        g_lpb[warp] = fmaf(blank, LOG2EF, -lse2);
        int u = warp & (UU - 1);
        if (u < UU - 1) {
            int b   = warp >> 13;
            int lab = labels[b * (UU - 1) + u];
            g_lpl[warp] = fmaf(base[lab], LOG2EF, -lse2);
        }
    }
}

// ---------------------------------------------------------------------------
// Phase 2+3: 2-diagonal-fused DP (95 super-steps), one warp/batch, 2 cells
// per lane. This round:
//  * weights packed float4 (A,B,C,-) -> 2x LDS.128/step, PREFETCHED one
//    iteration ahead (LDS latency hidden under the math chain)
//  * freeze folded into weights: t > T-1 => (A=0, B=C=NEG) makes the update
//    an exact identity (ex2(NEG-M)=0, lg2(1)=0) -> no selects in the loop
//  * unroll 2 for branch amortization
// All sources are from super-diag s-1, so the two cells per lane are
// independent within a step; the only chained op is the shfl.
// smem (floats): lpb[0,8192) lpl[8192,16384) wq[16384 .. +4*(6144+128))
// ---------------------------------------------------------------------------
__global__ void __launch_bounds__(256) dp_kernel(float* __restrict__ out) {
    int b = blockIdx.x;
    extern __shared__ float sm[];
    float*  s_lpb = sm;
    float*  s_lpl = sm + 8192;
    float4* wq    = (float4*)(sm + 16384);   // 6144 + 128 pad entries
    int tid = threadIdx.x;

    // Stage lp tables (float4, front-batched).
    {
        const float4* gb = (const float4*)(g_lpb + b * TT * UU);
        const float4* gl = (const float4*)(g_lpl + b * TT * UU);
        float4* sb = (float4*)s_lpb;
        float4* sl = (float4*)s_lpl;
        float4 rb[8], rl[8];
#pragma unroll
        for (int i = 0; i < 8; i++) {
            rb[i] = __ldcg(&gb[i * 256 + tid]);
            rl[i] = __ldcg(&gl[i * 256 + tid]);
        }
#pragma unroll
        for (int i = 0; i < 8; i++) {
            sb[i * 256 + tid] = rb[i];
            sl[i * 256 + tid] = rl[i];
        }
    }
    __syncthreads();

    // Build fused weights for s in [1,95], u in [0,63]: j = s*64 + u.
    for (int j = 64 + tid; j < 6144; j += 256) {
        int s = j >> 6, u = j & 63;
        int t = 2 * s - u;
        int r0 = min(max(t,     0), TT - 1);
        int r1 = min(max(t - 1, 0), TT - 1);
        int r2 = min(max(t - 2, 0), TT - 1);
        int um1 = max(u - 1, 0);
        int um2 = max(u - 2, 0);

        float b_r1u   = s_lpb[r1 * UU + u];
        float A       = s_lpb[r2 * UU + u] + b_r1u;
        float l_r0um1 = s_lpl[r0 * UU + um1];
        float B1 = s_lpl[r1 * UU + um1] + b_r1u;     // label@(t-1) then blank
        float B2 = s_lpb[r1 * UU + um1] + l_r0um1;   // blank@(t-1) then label
        float MBv = fmaxf(B1, B2);
        float B  = MBv + fast_lg2(fast_ex2(B1 - MBv) + fast_ex2(B2 - MBv));
        float C  = s_lpl[r0 * UU + um2] + l_r0um1;
        if (u == 0) B = NEGF;
        if (u < 2)  C = NEGF;
        if (t > TT - 1) { A = 0.f; B = NEGF; C = NEGF; }   // exact freeze
        wq[j] = make_float4(A, B, C, 0.f);
    }
    // pad region (prefetch overrun at s=95 reads s=96 row)
    if (tid < 128) wq[6144 + tid] = make_float4(0.f, NEGF, NEGF, 0.f);
    __syncthreads();
    if (tid >= 32) return;              // warp 0 runs the serial DP

    int lane = tid;
    int u_lo = lane * 2;

    // s=0 state: only alpha[0,0] = 0 live.
    float a_lo = (lane == 0) ? 0.f : NEGF;
    float a_hi = NEGF;
    float nl_lo = __shfl_up_sync(0xffffffffu, a_lo, 1);
    float nl_hi = __shfl_up_sync(0xffffffffu, a_hi, 1);

    int W = 64 + u_lo;
    float4 w0 = wq[W], w1 = wq[W + 1];

#pragma unroll 2
    for (int s = 1; s <= 95; s++) {
        float4 nw0 = wq[W + 64];        // prefetch next step's weights
        float4 nw1 = wq[W + 65];

        float x0 = a_lo  + w0.x;
        float y0 = nl_hi + w0.y;
        float z0 = nl_lo + w0.z;
        float x1 = a_hi  + w1.x;
        float y1 = a_lo  + w1.y;        // pre-update a_lo (s-1 value)
        float z1 = nl_hi + w1.z;

        float M0 = fmaxf(fmaxf(x0, y0), z0);
        float e0 = fast_ex2(x0 - M0) + fast_ex2(y0 - M0) + fast_ex2(z0 - M0);
        a_lo = M0 + fast_lg2(e0);

        float M1 = fmaxf(fmaxf(x1, y1), z1);
        float e1 = fast_ex2(x1 - M1) + fast_ex2(y1 - M1) + fast_ex2(z1 - M1);
        a_hi = M1 + fast_lg2(e1);

        nl_lo = __shfl_up_sync(0xffffffffu, a_lo, 1);
        nl_hi = __shfl_up_sync(0xffffffffu, a_hi, 1);

        w0 = nw0; w1 = nw1; W += 64;
    }

    // lane 31 a_hi = alpha[T-1, U-1]; add final blank, back to nat domain.
    int is_last = 0;
    if (lane == 31) {
        g_cost[b] = -(a_hi + s_lpb[(TT - 1) * UU + (UU - 1)]) * LN2F;
        __threadfence();
        is_last = (atomicAdd(&g_ticket, 1) == BB - 1);
    }
    is_last = __shfl_sync(0xffffffffu, is_last, 31);

    if (is_last) {
        float v = (lane < BB) ? __ldcg(&g_cost[lane]) : 0.f;
#pragma unroll
        for (int o = 16; o; o >>= 1)
            v += __shfl_xor_sync(0xffffffffu, v, o);
        if (lane == 0) {
            out[0] = v * (1.0f / BB);
            g_ticket = 0;                // reset for next graph replay
        }
    }
}

extern "C" void kernel_launch(void* const* d_in, const int* in_sizes, int n_in,
                              void* d_out, int out_size) {
    const float* acts   = (const float*)d_in[0];
    const int*   labels = (const int*)d_in[1];

    const int smem_bytes = (16384 + 4 * (6144 + 128)) * (int)sizeof(float); // 165888
    cudaFuncSetAttribute(dp_kernel, cudaFuncAttributeMaxDynamicSharedMemorySize,
                         smem_bytes);

    lse_kernel<<<CELLS / 8, 256>>>(acts, labels);
    dp_kernel<<<BB, 256, smem_bytes>>>((float*)d_out);
}